// round 8
// baseline (speedup 1.0000x reference)
#include <cuda_runtime.h>
#include <cuda_bf16.h>
#include <cstdint>

// Problem constants
#define BATCH   4
#define SEQ     6144
#define DIM     384
#define FCHUNK  3
#define NB      12      // BATCH*FCHUNK
#define LEN     2048    // SEQ/FCHUNK
#define DIN     192     // DIM/2
#define DSTATE  16
#define DTRANK  24
#define MTOT    (NB*LEN)    // 24576
#define NSEG    4
#define SEGLEN  (LEN/NSEG)  // 512

// ---------------------------------------------------------------------------
// Scratch (static __device__ arrays; no allocation allowed)
// ---------------------------------------------------------------------------
__device__ float g_xp[MTOT * DIM];           // (12,2048,384) in_proj output
__device__ float g_xc[NB * DIN * LEN];       // (b,d,l) conv+silu output
__device__ float g_dt[NB * DTRANK * LEN];    // (b,r,l)
__device__ float g_Bm[NB * LEN * DSTATE];    // (b,l,n)
__device__ float g_Cm[NB * LEN * DSTATE];    // (b,l,n)
__device__ float g_delta[NB * DIN * LEN];    // (b,d,l)
__device__ float g_yf[NB * DIN * LEN];       // fwd scan out; later fused ysum
__device__ float g_yb[NB * DIN * LEN];       // bwd scan out (b,d,l)
__device__ float g_hend[2 * NB * DIN * NSEG * DSTATE];  // seg-local final h
__device__ float g_sumd[NB * DIN * NSEG];               // per-seg sum(delta)
__device__ float g_hin[2 * NB * DIN * NSEG * DSTATE];   // seg entry states

// ---------------------------------------------------------------------------
// helpers
// ---------------------------------------------------------------------------
__device__ __forceinline__ uint32_t smem_u32(const void* p) {
    uint32_t a;
    asm("{ .reg .u64 t; cvta.to.shared.u64 t, %1; cvt.u32.u64 %0, t; }"
        : "=r"(a) : "l"(p));
    return a;
}
__device__ __forceinline__ uint32_t f2tf32(float x) {
    uint32_t r;
    asm("cvt.rna.tf32.f32 %0, %1;" : "=r"(r) : "f"(x));
    return r;
}
__device__ __forceinline__ void cp16(uint32_t dst, const void* src) {
    asm volatile("cp.async.ca.shared.global [%0], [%1], 16;"
                 :: "r"(dst), "l"(src) : "memory");
}
#define CP_COMMIT() asm volatile("cp.async.commit_group;" ::: "memory")
#define CP_WAIT1()  asm volatile("cp.async.wait_group 1;" ::: "memory")

__device__ __forceinline__ void mma_tf32(float* c, const uint32_t* a,
                                         const uint32_t* b) {
    asm volatile(
        "mma.sync.aligned.m16n8k8.row.col.f32.tf32.tf32.f32 "
        "{%0,%1,%2,%3}, {%4,%5,%6,%7}, {%8,%9}, {%0,%1,%2,%3};"
        : "+f"(c[0]), "+f"(c[1]), "+f"(c[2]), "+f"(c[3])
        : "r"(a[0]), "r"(a[1]), "r"(a[2]), "r"(a[3]), "r"(b[0]), "r"(b[1]));
}

// ---------------------------------------------------------------------------
// tf32 HMMA GEMM (R6-validated, 3-stage): C[M,384] = A[M,384]@W[384,384]^T+b
// ---------------------------------------------------------------------------
#define AS_STRIDE0 36
#define AS_STRIDE1 136
#define BS_STRIDE  36
#define AS_F0 (128 * AS_STRIDE0)
#define AS_F1 (32 * AS_STRIDE1)
#define BS_F  (128 * BS_STRIDE)
#define GEMM_SMEM0 ((3 * (AS_F0 + BS_F)) * 4)   // 110592 B
#define GEMM_SMEM1 ((3 * (AS_F1 + BS_F)) * 4)   // 107520 B

template <int MODE>
__global__ __launch_bounds__(256, 2)
void gemm_tf32_kernel(const float* __restrict__ A,
                      const float* __restrict__ W,
                      const float* __restrict__ bias,
                      float* __restrict__ C)
{
    extern __shared__ float smf[];
    constexpr int AS_F = (MODE == 0) ? AS_F0 : AS_F1;
    float* AsBuf = smf;
    float* BsBuf = smf + 3 * AS_F;

    const int tid  = threadIdx.x;
    const int wid  = tid >> 5;
    const int lane = tid & 31;
    const int g = lane >> 2;
    const int t = lane & 3;
    const int wm = wid >> 1;
    const int wn = wid & 1;

    const int m0 = blockIdx.y * 128;
    const int n0 = blockIdx.x * 128;
    const int bb = m0 >> 11;
    const int lbase = m0 & 2047;

    const uint32_t sAu = smem_u32(AsBuf);
    const uint32_t sBu = smem_u32(BsBuf);

    float acc[2][8][4];
#pragma unroll
    for (int mt = 0; mt < 2; mt++)
#pragma unroll
        for (int nt = 0; nt < 8; nt++)
#pragma unroll
            for (int q = 0; q < 4; q++) acc[mt][nt][q] = 0.f;

    auto load_tile = [&](int kt, int buf) {
        const int k0 = kt * 32;
#pragma unroll
        for (int it = 0; it < 4; it++) {
            int idx = it * 256 + tid;
            int r = idx >> 3, c4 = idx & 7;
            uint32_t dst = sBu + (buf * BS_F + r * BS_STRIDE + c4 * 4) * 4;
            cp16(dst, &W[(n0 + r) * DIM + k0 + c4 * 4]);
        }
        if (MODE == 0) {
#pragma unroll
            for (int it = 0; it < 4; it++) {
                int idx = it * 256 + tid;
                int r = idx >> 3, c4 = idx & 7;
                uint32_t dst = sAu + (buf * AS_F + r * AS_STRIDE0 + c4 * 4) * 4;
                cp16(dst, &A[(m0 + r) * DIM + k0 + c4 * 4]);
            }
        } else {
            const float* srcb = (k0 < DIN)
                ? g_yf + ((size_t)(bb * DIN + k0) * LEN)
                : g_xc + ((size_t)(bb * DIN + (k0 - DIN)) * LEN);
#pragma unroll
            for (int it = 0; it < 4; it++) {
                int idx = it * 256 + tid;
                int kk = idx >> 5, m4 = idx & 31;
                uint32_t dst = sAu + (buf * AS_F + kk * AS_STRIDE1 + m4 * 4) * 4;
                cp16(dst, srcb + (size_t)kk * LEN + lbase + m4 * 4);
            }
        }
        CP_COMMIT();
    };

    load_tile(0, 0);
    load_tile(1, 1);

    for (int kt = 0; kt < 12; kt++) {
        CP_WAIT1();
        __syncthreads();

        if (kt + 2 < 12) load_tile(kt + 2, (kt + 2) % 3);
        else CP_COMMIT();

        const int buf = kt % 3;
        const float* As = AsBuf + buf * AS_F;
        const float* Bs = BsBuf + buf * BS_F;

#pragma unroll
        for (int s = 0; s < 4; s++) {
            uint32_t bf[8][2];
#pragma unroll
            for (int nt = 0; nt < 8; nt++) {
                int n = wn * 64 + nt * 8 + g;
                bf[nt][0] = f2tf32(Bs[n * BS_STRIDE + s * 8 + t]);
                bf[nt][1] = f2tf32(Bs[n * BS_STRIDE + s * 8 + t + 4]);
            }
#pragma unroll
            for (int mt = 0; mt < 2; mt++) {
                int row = wm * 32 + mt * 16 + g;
                uint32_t af[4];
                if (MODE == 0) {
                    af[0] = f2tf32(As[row * AS_STRIDE0 + s * 8 + t]);
                    af[1] = f2tf32(As[(row + 8) * AS_STRIDE0 + s * 8 + t]);
                    af[2] = f2tf32(As[row * AS_STRIDE0 + s * 8 + t + 4]);
                    af[3] = f2tf32(As[(row + 8) * AS_STRIDE0 + s * 8 + t + 4]);
                } else {
                    af[0] = f2tf32(As[(s * 8 + t) * AS_STRIDE1 + row]);
                    af[1] = f2tf32(As[(s * 8 + t) * AS_STRIDE1 + row + 8]);
                    af[2] = f2tf32(As[(s * 8 + t + 4) * AS_STRIDE1 + row]);
                    af[3] = f2tf32(As[(s * 8 + t + 4) * AS_STRIDE1 + row + 8]);
                }
#pragma unroll
                for (int nt = 0; nt < 8; nt++)
                    mma_tf32(acc[mt][nt], af, bf[nt]);
            }
        }
        __syncthreads();
    }

#pragma unroll
    for (int mt = 0; mt < 2; mt++) {
        int row = m0 + wm * 32 + mt * 16 + g;
#pragma unroll
        for (int nt = 0; nt < 8; nt++) {
            int col = n0 + wn * 64 + nt * 8 + t * 2;
            float b0 = bias[col], b1 = bias[col + 1];
            float2 v0 = make_float2(acc[mt][nt][0] + b0, acc[mt][nt][1] + b1);
            float2 v1 = make_float2(acc[mt][nt][2] + b0, acc[mt][nt][3] + b1);
            *(float2*)&C[(size_t)row * DIM + col] = v0;
            *(float2*)&C[(size_t)(row + 8) * DIM + col] = v1;
        }
    }
}

// ---------------------------------------------------------------------------
// Grouped conv (k=3, SAME, groups=192, 2 in-ch per group) + SiLU
// ---------------------------------------------------------------------------
__global__ __launch_bounds__(1024)
void conv_silu_kernel(const float* __restrict__ conv_w,
                      const float* __restrict__ conv_b)
{
    __shared__ float s[34][65];
    const int b  = blockIdx.z;
    const int d0 = blockIdx.y * 32;
    const int l0 = blockIdx.x * 32;
    const int tid = threadIdx.y * 32 + threadIdx.x;

    for (int e = tid; e < 34 * 64; e += 1024) {
        int li = e >> 6;
        int ci = e & 63;
        int l = l0 - 1 + li;
        float v = 0.f;
        if (l >= 0 && l < LEN)
            v = g_xp[(b * LEN + l) * DIM + 2 * d0 + ci];
        s[li][ci] = v;
    }
    __syncthreads();

    const int tx = threadIdx.x, ty = threadIdx.y;
    const int d = d0 + ty;
    float acc = conv_b[d];
    const float* w = conv_w + d * 6;
#pragma unroll
    for (int i = 0; i < 2; i++)
#pragma unroll
        for (int j = 0; j < 3; j++)
            acc = fmaf(s[tx + j][2 * ty + i], w[i * 3 + j], acc);
    float y = acc / (1.f + __expf(-acc));
    g_xc[(b * DIN + d) * LEN + l0 + tx] = y;
}

// ---------------------------------------------------------------------------
// x_proj: x_dbl[b,r,l] = sum_d W[r,d]*xc[b,d,l]; r-chunked over blockIdx.z
// ---------------------------------------------------------------------------
__global__ __launch_bounds__(128)
void xproj_kernel(const float* __restrict__ x_proj_w)
{
    __shared__ float sW[14 * DIN];
    const int b = blockIdx.y;
    const int l = blockIdx.x * 128 + threadIdx.x;
    const int r0 = blockIdx.z * 14;

    for (int i = threadIdx.x; i < 14 * DIN; i += 128)
        sW[i] = x_proj_w[r0 * DIN + i];
    __syncthreads();

    float acc[14];
#pragma unroll
    for (int j = 0; j < 14; j++) acc[j] = 0.f;

    for (int d = 0; d < DIN; d++) {
        float v = g_xc[(b * DIN + d) * LEN + l];
#pragma unroll
        for (int j = 0; j < 14; j++)
            acc[j] = fmaf(sW[j * DIN + d], v, acc[j]);
    }
#pragma unroll
    for (int j = 0; j < 14; j++) {
        int r = r0 + j;
        if (r < DTRANK)
            g_dt[(b * DTRANK + r) * LEN + l] = acc[j];
        else if (r < DTRANK + DSTATE)
            g_Bm[(b * LEN + l) * DSTATE + (r - DTRANK)] = acc[j];
        else
            g_Cm[(b * LEN + l) * DSTATE + (r - DTRANK - DSTATE)] = acc[j];
    }
}

// ---------------------------------------------------------------------------
// delta[b,d,l] = softplus(dt_proj_w[d,:].dt[b,:,l] + dt_proj_b[d]); d-chunk 24
// ---------------------------------------------------------------------------
__global__ __launch_bounds__(128)
void delta_kernel(const float* __restrict__ dt_proj_w,
                  const float* __restrict__ dt_proj_b)
{
    __shared__ float sW[24 * DTRANK];
    const int b = blockIdx.y;
    const int l = blockIdx.x * 128 + threadIdx.x;
    const int d0 = blockIdx.z * 24;

    for (int i = threadIdx.x; i < 24 * DTRANK; i += 128)
        sW[i] = dt_proj_w[d0 * DTRANK + i];
    __syncthreads();

    float dt[DTRANK];
#pragma unroll
    for (int r = 0; r < DTRANK; r++)
        dt[r] = g_dt[(b * DTRANK + r) * LEN + l];

#pragma unroll 4
    for (int j = 0; j < 24; j++) {
        int d = d0 + j;
        float a = dt_proj_b[d];
#pragma unroll
        for (int r = 0; r < DTRANK; r++)
            a = fmaf(sW[j * DTRANK + r], dt[r], a);
        float sp = (a > 20.f) ? a : log1pf(__expf(a));
        g_delta[(b * DIN + d) * LEN + l] = sp;
    }
}

// ---------------------------------------------------------------------------
// Segmented scan, pass A: per-segment local final state + sum(delta).
// Block: 256 thr, (b, 8 d's, seg). Warps 0-3 fwd (2 d each, 16 lanes/d),
// warps 4-7 bwd. No C loads, no y output, no shfl.
// smem/buffer: Bf[64][16] Bb (2048) + del/u f/b [8][68]x4 (2176) = 4224 fl.
// ---------------------------------------------------------------------------
#define SA_BUF  4224
#define SA_SMEM (2 * SA_BUF * 4)   // 33792 B

__global__ __launch_bounds__(256)
void scanA_kernel(const float* __restrict__ A_log,
                  const float* __restrict__ Ab_log)
{
    extern __shared__ float ss[];
    const int bid = blockIdx.x;
    const int seg = bid & (NSEG - 1);
    const int rem = bid >> 2;
    const int b  = rem / (DIN / 8);
    const int d0 = (rem % (DIN / 8)) * 8;
    const int tid = threadIdx.x;
    const int wid = tid >> 5, lane = tid & 31;
    const bool bwd = wid >= 4;
    const int w = bwd ? wid - 4 : wid;
    const int half = lane >> 4, n = lane & 15;
    const int dloc = 2 * w + half;
    const int dg = d0 + dloc;
    const int segbase = seg * SEGLEN;

    const float Aval = -__expf(bwd ? Ab_log[dg * DSTATE + n]
                                   : A_log[dg * DSTATE + n]);
    const uint32_t sbase = smem_u32(ss);

    auto load_chunk = [&](int c, int buf) {
        const uint32_t dstb = sbase + (uint32_t)buf * SA_BUF * 4;
        const int lf = segbase + c * 64;
        const int lb = segbase + SEGLEN - (c + 1) * 64;
        // B fwd/bwd: 512 float4 tasks, 2/thread
#pragma unroll
        for (int it = 0; it < 2; it++) {
            int task = it * 256 + tid;
            int arr = task >> 8, r = task & 255;
            int lo = r >> 2, n4 = (r & 3) * 4;
            int ls = arr ? lb + lo : lf + lo;
            cp16(dstb + (uint32_t)(arr * 1024 + lo * 16 + n4) * 4,
                 g_Bm + ((size_t)(b * LEN + ls) * DSTATE + n4));
        }
        // del/u f/b: 512 float4 tasks, 2/thread
#pragma unroll
        for (int it = 0; it < 2; it++) {
            int q = it * 256 + tid;
            int arr = q >> 7, s2 = q & 127;
            int dd = s2 >> 4, l4 = (s2 & 15) * 4;
            int ls = (arr < 2) ? lf + l4 : lb + l4;
            const float* src = ((arr & 1) ? g_xc : g_delta)
                + ((size_t)(b * DIN + d0 + dd) * LEN + ls);
            cp16(dstb + (uint32_t)(2048 + arr * 544 + dd * 68 + l4) * 4, src);
        }
    };

    float h = 0.f, sd = 0.f;
    load_chunk(0, 0);
    CP_COMMIT();

    for (int c = 0; c < SEGLEN / 64; c++) {
        const int buf = c & 1;
        if (c + 1 < SEGLEN / 64) load_chunk(c + 1, buf ^ 1);
        CP_COMMIT();
        CP_WAIT1();
        __syncthreads();

        const float* sm   = ss + buf * SA_BUF;
        const float* sB   = sm + (bwd ? 1024 : 0);
        const float* sdel = sm + 2048 + (bwd ? 1088 : 0) + dloc * 68;
        const float* su   = sdel + 544;

#pragma unroll 4
        for (int j4 = 0; j4 < 16; j4++) {
            const int toff = bwd ? (15 - j4) * 4 : j4 * 4;
            float4 d4 = *(const float4*)&sdel[toff];
            float4 u4 = *(const float4*)&su[toff];
            float dv[4] = {d4.x, d4.y, d4.z, d4.w};
            float uv[4] = {u4.x, u4.y, u4.z, u4.w};
#pragma unroll
            for (int k = 0; k < 4; k++) {
                int kk = bwd ? 3 - k : k;
                int t = toff + kk;
                float del = dv[kk], u = uv[kk];
                float Bv = sB[t * 16 + n];
                float dA = __expf(del * Aval);
                h = fmaf(dA, h, del * u * Bv);
                sd += del;
            }
        }
        __syncthreads();
    }

    g_hend[((((bwd ? 1 : 0) * NB + b) * DIN + dg) * NSEG + seg) * DSTATE + n] = h;
    if (!bwd && n == 0)
        g_sumd[(b * DIN + dg) * NSEG + seg] = sd;
}

// ---------------------------------------------------------------------------
// Segmented scan, pass B: combine segment summaries into entry states.
// One thread per (dir, b, d, n) = 73728 threads.
// ---------------------------------------------------------------------------
__global__ __launch_bounds__(256)
void scanB_kernel(const float* __restrict__ A_log,
                  const float* __restrict__ Ab_log)
{
    const int idx = blockIdx.x * 256 + threadIdx.x;
    if (idx >= 2 * NB * DIN * DSTATE) return;
    const int n = idx & 15;
    const int d = (idx >> 4) % DIN;
    const int b = ((idx >> 4) / DIN) % NB;
    const int dir = idx / (DSTATE * DIN * NB);

    const float Aval = -__expf((dir ? Ab_log : A_log)[d * DSTATE + n]);
    const size_t base = (((size_t)dir * NB + b) * DIN + d) * NSEG;
    const float* sd = g_sumd + (size_t)(b * DIN + d) * NSEG;

    float hin = 0.f;
    if (dir == 0) {
        for (int s = 0; s < NSEG; s++) {
            g_hin[(base + s) * DSTATE + n] = hin;
            float P = __expf(Aval * sd[s]);
            hin = fmaf(P, hin, g_hend[(base + s) * DSTATE + n]);
        }
    } else {
        for (int s = NSEG - 1; s >= 0; s--) {
            g_hin[(base + s) * DSTATE + n] = hin;
            float P = __expf(Aval * sd[s]);
            hin = fmaf(P, hin, g_hend[(base + s) * DSTATE + n]);
        }
    }
}

// ---------------------------------------------------------------------------
// Segmented scan, pass C: full scan per segment with h_in, emits y.
// v2 body; block (b, 8 d's, seg), 256 thr, 8 chunks of 64.
// smem/buffer: Bf Cf Bb Cb [64][16] (4096) + del/u f/b [8][68] (2176) = 6272.
// ---------------------------------------------------------------------------
#define SC_BUF   6272
#define SC_DU    4096
#define SC_SMEM  (2 * SC_BUF * 4)   // 50176 B

__global__ __launch_bounds__(256)
void scanC_kernel(const float* __restrict__ A_log,
                  const float* __restrict__ Ab_log)
{
    extern __shared__ float ss[];
    const int bid = blockIdx.x;
    const int seg = bid & (NSEG - 1);
    const int rem = bid >> 2;
    const int b  = rem / (DIN / 8);
    const int d0 = (rem % (DIN / 8)) * 8;
    const int tid = threadIdx.x;
    const int wid = tid >> 5, lane = tid & 31;
    const bool bwd = wid >= 4;
    const int w = bwd ? wid - 4 : wid;
    const int half = lane >> 4, n = lane & 15;
    const int dloc = 2 * w + half;
    const int dg = d0 + dloc;
    const int segbase = seg * SEGLEN;

    const float Aval = -__expf(bwd ? Ab_log[dg * DSTATE + n]
                                   : A_log[dg * DSTATE + n]);
    float* yptr = (bwd ? g_yb : g_yf) + (size_t)(b * DIN + dg) * LEN;
    const uint32_t sbase = smem_u32(ss);

    auto load_chunk = [&](int c, int buf) {
        const uint32_t dstb = sbase + (uint32_t)buf * SC_BUF * 4;
        const int lf = segbase + c * 64;
        const int lb = segbase + SEGLEN - (c + 1) * 64;
#pragma unroll
        for (int it = 0; it < 4; it++) {
            int task = it * 256 + tid;
            int arr = task >> 8, r = task & 255;
            int lo = r >> 2, n4 = (r & 3) * 4;
            int ls = (arr < 2) ? lf + lo : lb + lo;
            const float* src = ((arr & 1) ? g_Cm : g_Bm)
                + ((size_t)(b * LEN + ls) * DSTATE + n4);
            cp16(dstb + (uint32_t)(arr * 1024 + lo * 16 + n4) * 4, src);
        }
#pragma unroll
        for (int it = 0; it < 2; it++) {
            int q = it * 256 + tid;
            int arr = q >> 7, s2 = q & 127;
            int dd = s2 >> 4, l4 = (s2 & 15) * 4;
            int ls = (arr < 2) ? lf + l4 : lb + l4;
            const float* src = ((arr & 1) ? g_xc : g_delta)
                + ((size_t)(b * DIN + d0 + dd) * LEN + ls);
            cp16(dstb + (uint32_t)(SC_DU + arr * 544 + dd * 68 + l4) * 4, src);
        }
    };

    float h = g_hin[((((bwd ? 1 : 0) * NB + b) * DIN + dg) * NSEG + seg)
                    * DSTATE + n];

    load_chunk(0, 0);
    CP_COMMIT();

    for (int c = 0; c < SEGLEN / 64; c++) {
        const int buf = c & 1;
        if (c + 1 < SEGLEN / 64) load_chunk(c + 1, buf ^ 1);
        CP_COMMIT();
        CP_WAIT1();
        __syncthreads();

        const float* sm   = ss + buf * SC_BUF;
        const float* sB   = sm + (bwd ? 2048 : 0);
        const float* sC   = sB + 1024;
        const float* sdel = sm + SC_DU + (bwd ? 1088 : 0) + dloc * 68;
        const float* su   = sdel + 544;

        const int tg = bwd ? (segbase + SEGLEN - (c + 1) * 64)
                           : (segbase + c * 64);

#pragma unroll 4
        for (int j4 = 0; j4 < 16; j4++) {
            const int toff = bwd ? (15 - j4) * 4 : j4 * 4;
            float4 d4 = *(const float4*)&sdel[toff];
            float4 u4 = *(const float4*)&su[toff];
            float dv[4] = {d4.x, d4.y, d4.z, d4.w};
            float uv[4] = {u4.x, u4.y, u4.z, u4.w};
            float p[4];
#pragma unroll
            for (int k = 0; k < 4; k++) {
                int kk = bwd ? 3 - k : k;
                int t = toff + kk;
                float del = dv[kk], u = uv[kk];
                float Bv = sB[t * 16 + n];
                float Cv = sC[t * 16 + n];
                float dA = __expf(del * Aval);
                h = fmaf(dA, h, del * u * Bv);
                p[kk] = h * Cv;
            }
#pragma unroll
            for (int k = 0; k < 4; k++) {
                p[k] += __shfl_xor_sync(0xffffffffu, p[k], 1);
                p[k] += __shfl_xor_sync(0xffffffffu, p[k], 2);
                p[k] += __shfl_xor_sync(0xffffffffu, p[k], 4);
                p[k] += __shfl_xor_sync(0xffffffffu, p[k], 8);
            }
            if (n == 0)
                *(float4*)&yptr[tg + (toff & ~3) ] =
                    make_float4(p[0], p[1], p[2], p[3]);
        }
        __syncthreads();
    }
}

// ---------------------------------------------------------------------------
// fuse: g_yf = yf + yb + 2*D[d]*xc   (elementwise, (b,d,l) layout)
// ---------------------------------------------------------------------------
__global__ __launch_bounds__(256)
void fuse_kernel(const float* __restrict__ Dv)
{
    const int total4 = NB * DIN * LEN / 4;
    for (int i4 = blockIdx.x * blockDim.x + threadIdx.x; i4 < total4;
         i4 += gridDim.x * blockDim.x) {
        int d = (i4 >> 9) % DIN;
        float dd = 2.f * Dv[d];
        float4 yf4 = ((const float4*)g_yf)[i4];
        float4 yb4 = ((const float4*)g_yb)[i4];
        float4 xc4 = ((const float4*)g_xc)[i4];
        float4 o;
        o.x = yf4.x + yb4.x + dd * xc4.x;
        o.y = yf4.y + yb4.y + dd * xc4.y;
        o.z = yf4.z + yb4.z + dd * xc4.z;
        o.w = yf4.w + yb4.w + dd * xc4.w;
        ((float4*)g_yf)[i4] = o;
    }
}

// ---------------------------------------------------------------------------
// Launch
// ---------------------------------------------------------------------------
extern "C" void kernel_launch(void* const* d_in, const int* in_sizes, int n_in,
                              void* d_out, int out_size)
{
    (void)in_sizes; (void)n_in; (void)out_size;
    const float* x          = (const float*)d_in[0];
    const float* in_proj_w  = (const float*)d_in[1];
    const float* in_proj_b  = (const float*)d_in[2];
    const float* conv_w     = (const float*)d_in[3];
    const float* conv_b     = (const float*)d_in[4];
    const float* A_log      = (const float*)d_in[5];
    const float* Ab_log     = (const float*)d_in[6];
    const float* Dv         = (const float*)d_in[7];
    const float* x_proj_w   = (const float*)d_in[8];
    const float* dt_proj_w  = (const float*)d_in[9];
    const float* dt_proj_b  = (const float*)d_in[10];
    const float* out_proj_w = (const float*)d_in[11];
    const float* out_proj_b = (const float*)d_in[12];
    float* out = (float*)d_out;

    float* xp_ptr;
    cudaGetSymbolAddress((void**)&xp_ptr, g_xp);

    cudaFuncSetAttribute(gemm_tf32_kernel<0>,
                         cudaFuncAttributeMaxDynamicSharedMemorySize, GEMM_SMEM0);
    cudaFuncSetAttribute(gemm_tf32_kernel<1>,
                         cudaFuncAttributeMaxDynamicSharedMemorySize, GEMM_SMEM1);
    cudaFuncSetAttribute(scanA_kernel,
                         cudaFuncAttributeMaxDynamicSharedMemorySize, SA_SMEM);
    cudaFuncSetAttribute(scanC_kernel,
                         cudaFuncAttributeMaxDynamicSharedMemorySize, SC_SMEM);

    // 1. in_proj GEMM (tf32 HMMA, 3-stage) -> g_xp
    gemm_tf32_kernel<0><<<dim3(DIM / 128, MTOT / 128), 256, GEMM_SMEM0>>>(
        x, in_proj_w, in_proj_b, xp_ptr);

    // 2. conv + silu -> g_xc
    conv_silu_kernel<<<dim3(LEN / 32, DIN / 32, NB), dim3(32, 32)>>>(
        conv_w, conv_b);

    // 3. x_proj split -> g_dt, g_Bm, g_Cm
    xproj_kernel<<<dim3(LEN / 128, NB, 4), 128>>>(x_proj_w);

    // 4. delta = softplus(dt_proj) -> g_delta   (profiled slot)
    delta_kernel<<<dim3(LEN / 128, NB, 8), 128>>>(dt_proj_w, dt_proj_b);

    // 5. scan pass A: segment summaries
    scanA_kernel<<<NB * (DIN / 8) * NSEG, 256, SA_SMEM>>>(A_log, Ab_log);

    // 6. scan pass B: combine entry states
    scanB_kernel<<<(2 * NB * DIN * DSTATE + 255) / 256, 256>>>(A_log, Ab_log);

    // 7. scan pass C: per-segment full scan (concurrent) -> g_yf, g_yb
    scanC_kernel<<<NB * (DIN / 8) * NSEG, 256, SC_SMEM>>>(A_log, Ab_log);

    // 8. fuse ysum = yf + yb + 2*D*xc -> g_yf
    fuse_kernel<<<1024, 256>>>(Dv);

    // 9. out_proj GEMM (tf32 HMMA, 3-stage, (d,l)-layout A) -> d_out
    gemm_tf32_kernel<1><<<dim3(DIM / 128, MTOT / 128), 256, GEMM_SMEM1>>>(
        nullptr, out_proj_w, out_proj_b, out);
}

// round 9
// speedup vs baseline: 2.0683x; 2.0683x over previous
#include <cuda_runtime.h>
#include <cuda_bf16.h>
#include <cstdint>

// Problem constants
#define BATCH   4
#define SEQ     6144
#define DIM     384
#define FCHUNK  3
#define NB      12      // BATCH*FCHUNK
#define LEN     2048    // SEQ/FCHUNK
#define DIN     192     // DIM/2
#define DSTATE  16
#define DTRANK  24
#define MTOT    (NB*LEN)    // 24576

// ---------------------------------------------------------------------------
// Scratch (static __device__ arrays; no allocation allowed)
// ---------------------------------------------------------------------------
__device__ float g_xp[MTOT * DIM];           // (12,2048,384) in_proj output
__device__ float g_xc[NB * DIN * LEN];       // (b,d,l) conv+silu output
__device__ float g_dt[NB * DTRANK * LEN];    // (b,r,l)
__device__ float g_Bm[NB * LEN * DSTATE];    // (b,l,n)
__device__ float g_Cm[NB * LEN * DSTATE];    // (b,l,n)
__device__ float g_delta[NB * DIN * LEN];    // (b,d,l)
__device__ float g_yf[NB * DIN * LEN];       // fwd scan out; later fused ysum
__device__ float g_yb[NB * DIN * LEN];       // bwd scan out (b,d,l)

// ---------------------------------------------------------------------------
// helpers
// ---------------------------------------------------------------------------
__device__ __forceinline__ uint32_t smem_u32(const void* p) {
    uint32_t a;
    asm("{ .reg .u64 t; cvta.to.shared.u64 t, %1; cvt.u32.u64 %0, t; }"
        : "=r"(a) : "l"(p));
    return a;
}
__device__ __forceinline__ uint32_t f2tf32(float x) {
    uint32_t r;
    asm("cvt.rna.tf32.f32 %0, %1;" : "=r"(r) : "f"(x));
    return r;
}
__device__ __forceinline__ void cp16(uint32_t dst, const void* src) {
    asm volatile("cp.async.ca.shared.global [%0], [%1], 16;"
                 :: "r"(dst), "l"(src) : "memory");
}
#define CP_COMMIT() asm volatile("cp.async.commit_group;" ::: "memory")
#define CP_WAIT1()  asm volatile("cp.async.wait_group 1;" ::: "memory")
#define CP_WAIT0()  asm volatile("cp.async.wait_group 0;" ::: "memory")

__device__ __forceinline__ void mma_tf32(float* c, const uint32_t* a,
                                         const uint32_t* b) {
    asm volatile(
        "mma.sync.aligned.m16n8k8.row.col.f32.tf32.tf32.f32 "
        "{%0,%1,%2,%3}, {%4,%5,%6,%7}, {%8,%9}, {%0,%1,%2,%3};"
        : "+f"(c[0]), "+f"(c[1]), "+f"(c[2]), "+f"(c[3])
        : "r"(a[0]), "r"(a[1]), "r"(a[2]), "r"(a[3]), "r"(b[0]), "r"(b[1]));
}

// ---------------------------------------------------------------------------
// tf32 HMMA GEMM: C[M,384] = A[M,384] @ W[384,384]^T + bias
// MODE 0: A plain row-major [m][k] (in_proj). MODE 1: A from (d,l) layout
// (k<192 -> g_yf fused ysum, else g_xc). 128x128 tile, BK=32,
// 2-stage cp.async pipeline (73.7KB smem -> 2 CTAs/SM).
// ---------------------------------------------------------------------------
#define AS_STRIDE0 36
#define AS_STRIDE1 136
#define BS_STRIDE  36
#define AS_F0 (128 * AS_STRIDE0)
#define AS_F1 (32 * AS_STRIDE1)
#define BS_F  (128 * BS_STRIDE)
#define GEMM_SMEM0 ((2 * (AS_F0 + BS_F)) * 4)   // 73728 B
#define GEMM_SMEM1 ((2 * (AS_F1 + BS_F)) * 4)   // 71680 B

template <int MODE>
__global__ __launch_bounds__(256, 2)
void gemm_tf32_kernel(const float* __restrict__ A,
                      const float* __restrict__ W,
                      const float* __restrict__ bias,
                      float* __restrict__ C)
{
    extern __shared__ float smf[];
    constexpr int AS_F = (MODE == 0) ? AS_F0 : AS_F1;
    float* AsBuf = smf;
    float* BsBuf = smf + 2 * AS_F;

    const int tid  = threadIdx.x;
    const int wid  = tid >> 5;
    const int lane = tid & 31;
    const int g = lane >> 2;
    const int t = lane & 3;
    const int wm = wid >> 1;
    const int wn = wid & 1;

    const int m0 = blockIdx.y * 128;
    const int n0 = blockIdx.x * 128;
    const int bb = m0 >> 11;
    const int lbase = m0 & 2047;

    const uint32_t sAu = smem_u32(AsBuf);
    const uint32_t sBu = smem_u32(BsBuf);

    float acc[2][8][4];
#pragma unroll
    for (int mt = 0; mt < 2; mt++)
#pragma unroll
        for (int nt = 0; nt < 8; nt++)
#pragma unroll
            for (int q = 0; q < 4; q++) acc[mt][nt][q] = 0.f;

    auto load_tile = [&](int kt, int buf) {
        const int k0 = kt * 32;
#pragma unroll
        for (int it = 0; it < 4; it++) {
            int idx = it * 256 + tid;
            int r = idx >> 3, c4 = idx & 7;
            uint32_t dst = sBu + (buf * BS_F + r * BS_STRIDE + c4 * 4) * 4;
            cp16(dst, &W[(n0 + r) * DIM + k0 + c4 * 4]);
        }
        if (MODE == 0) {
#pragma unroll
            for (int it = 0; it < 4; it++) {
                int idx = it * 256 + tid;
                int r = idx >> 3, c4 = idx & 7;
                uint32_t dst = sAu + (buf * AS_F + r * AS_STRIDE0 + c4 * 4) * 4;
                cp16(dst, &A[(m0 + r) * DIM + k0 + c4 * 4]);
            }
        } else {
            const float* srcb = (k0 < DIN)
                ? g_yf + ((size_t)(bb * DIN + k0) * LEN)
                : g_xc + ((size_t)(bb * DIN + (k0 - DIN)) * LEN);
#pragma unroll
            for (int it = 0; it < 4; it++) {
                int idx = it * 256 + tid;
                int kk = idx >> 5, m4 = idx & 31;
                uint32_t dst = sAu + (buf * AS_F + kk * AS_STRIDE1 + m4 * 4) * 4;
                cp16(dst, srcb + (size_t)kk * LEN + lbase + m4 * 4);
            }
        }
        CP_COMMIT();
    };

    load_tile(0, 0);

    for (int kt = 0; kt < 12; kt++) {
        if (kt + 1 < 12) {
            load_tile(kt + 1, (kt + 1) & 1);
            CP_WAIT1();
        } else {
            CP_WAIT0();
        }
        __syncthreads();

        const int buf = kt & 1;
        const float* As = AsBuf + buf * AS_F;
        const float* Bs = BsBuf + buf * BS_F;

#pragma unroll
        for (int s = 0; s < 4; s++) {
            uint32_t bf[8][2];
#pragma unroll
            for (int nt = 0; nt < 8; nt++) {
                int n = wn * 64 + nt * 8 + g;
                bf[nt][0] = f2tf32(Bs[n * BS_STRIDE + s * 8 + t]);
                bf[nt][1] = f2tf32(Bs[n * BS_STRIDE + s * 8 + t + 4]);
            }
#pragma unroll
            for (int mt = 0; mt < 2; mt++) {
                int row = wm * 32 + mt * 16 + g;
                uint32_t af[4];
                if (MODE == 0) {
                    af[0] = f2tf32(As[row * AS_STRIDE0 + s * 8 + t]);
                    af[1] = f2tf32(As[(row + 8) * AS_STRIDE0 + s * 8 + t]);
                    af[2] = f2tf32(As[row * AS_STRIDE0 + s * 8 + t + 4]);
                    af[3] = f2tf32(As[(row + 8) * AS_STRIDE0 + s * 8 + t + 4]);
                } else {
                    af[0] = f2tf32(As[(s * 8 + t) * AS_STRIDE1 + row]);
                    af[1] = f2tf32(As[(s * 8 + t) * AS_STRIDE1 + row + 8]);
                    af[2] = f2tf32(As[(s * 8 + t + 4) * AS_STRIDE1 + row]);
                    af[3] = f2tf32(As[(s * 8 + t + 4) * AS_STRIDE1 + row + 8]);
                }
#pragma unroll
                for (int nt = 0; nt < 8; nt++)
                    mma_tf32(acc[mt][nt], af, bf[nt]);
            }
        }
        __syncthreads();
    }

#pragma unroll
    for (int mt = 0; mt < 2; mt++) {
        int row = m0 + wm * 32 + mt * 16 + g;
#pragma unroll
        for (int nt = 0; nt < 8; nt++) {
            int col = n0 + wn * 64 + nt * 8 + t * 2;
            float b0 = bias[col], b1 = bias[col + 1];
            float2 v0 = make_float2(acc[mt][nt][0] + b0, acc[mt][nt][1] + b1);
            float2 v1 = make_float2(acc[mt][nt][2] + b0, acc[mt][nt][3] + b1);
            *(float2*)&C[(size_t)row * DIM + col] = v0;
            *(float2*)&C[(size_t)(row + 8) * DIM + col] = v1;
        }
    }
}

// ---------------------------------------------------------------------------
// Grouped conv (k=3, SAME, groups=192, 2 in-ch per group) + SiLU
// ---------------------------------------------------------------------------
__global__ __launch_bounds__(1024)
void conv_silu_kernel(const float* __restrict__ conv_w,
                      const float* __restrict__ conv_b)
{
    __shared__ float s[34][65];
    const int b  = blockIdx.z;
    const int d0 = blockIdx.y * 32;
    const int l0 = blockIdx.x * 32;
    const int tid = threadIdx.y * 32 + threadIdx.x;

    for (int e = tid; e < 34 * 64; e += 1024) {
        int li = e >> 6;
        int ci = e & 63;
        int l = l0 - 1 + li;
        float v = 0.f;
        if (l >= 0 && l < LEN)
            v = g_xp[(b * LEN + l) * DIM + 2 * d0 + ci];
        s[li][ci] = v;
    }
    __syncthreads();

    const int tx = threadIdx.x, ty = threadIdx.y;
    const int d = d0 + ty;
    float acc = conv_b[d];
    const float* w = conv_w + d * 6;
#pragma unroll
    for (int i = 0; i < 2; i++)
#pragma unroll
        for (int j = 0; j < 3; j++)
            acc = fmaf(s[tx + j][2 * ty + i], w[i * 3 + j], acc);
    float y = acc / (1.f + __expf(-acc));
    g_xc[(b * DIN + d) * LEN + l0 + tx] = y;
}

// ---------------------------------------------------------------------------
// x_proj: x_dbl[b,r,l] = sum_d W[r,d]*xc[b,d,l]; r-chunked over blockIdx.z
// ---------------------------------------------------------------------------
__global__ __launch_bounds__(128)
void xproj_kernel(const float* __restrict__ x_proj_w)
{
    __shared__ float sW[14 * DIN];
    const int b = blockIdx.y;
    const int l = blockIdx.x * 128 + threadIdx.x;
    const int r0 = blockIdx.z * 14;

    for (int i = threadIdx.x; i < 14 * DIN; i += 128)
        sW[i] = x_proj_w[r0 * DIN + i];
    __syncthreads();

    float acc[14];
#pragma unroll
    for (int j = 0; j < 14; j++) acc[j] = 0.f;

    for (int d = 0; d < DIN; d++) {
        float v = g_xc[(b * DIN + d) * LEN + l];
#pragma unroll
        for (int j = 0; j < 14; j++)
            acc[j] = fmaf(sW[j * DIN + d], v, acc[j]);
    }
#pragma unroll
    for (int j = 0; j < 14; j++) {
        int r = r0 + j;
        if (r < DTRANK)
            g_dt[(b * DTRANK + r) * LEN + l] = acc[j];
        else if (r < DTRANK + DSTATE)
            g_Bm[(b * LEN + l) * DSTATE + (r - DTRANK)] = acc[j];
        else
            g_Cm[(b * LEN + l) * DSTATE + (r - DTRANK - DSTATE)] = acc[j];
    }
}

// ---------------------------------------------------------------------------
// delta[b,d,l] = softplus(dt_proj_w[d,:].dt[b,:,l] + dt_proj_b[d]); d-chunk 24
// ---------------------------------------------------------------------------
__global__ __launch_bounds__(128)
void delta_kernel(const float* __restrict__ dt_proj_w,
                  const float* __restrict__ dt_proj_b)
{
    __shared__ float sW[24 * DTRANK];
    const int b = blockIdx.y;
    const int l = blockIdx.x * 128 + threadIdx.x;
    const int d0 = blockIdx.z * 24;

    for (int i = threadIdx.x; i < 24 * DTRANK; i += 128)
        sW[i] = dt_proj_w[d0 * DTRANK + i];
    __syncthreads();

    float dt[DTRANK];
#pragma unroll
    for (int r = 0; r < DTRANK; r++)
        dt[r] = g_dt[(b * DTRANK + r) * LEN + l];

#pragma unroll 4
    for (int j = 0; j < 24; j++) {
        int d = d0 + j;
        float a = dt_proj_b[d];
#pragma unroll
        for (int r = 0; r < DTRANK; r++)
            a = fmaf(sW[j * DTRANK + r], dt[r], a);
        float sp = (a > 20.f) ? a : log1pf(__expf(a));
        g_delta[(b * DIN + d) * LEN + l] = sp;
    }
}

// ---------------------------------------------------------------------------
// Bidirectional selective scan v2 (R6-validated) — smem-staged, cp.async
// double-buffered. Block: 256 thr / 8 warps, owns (b, 8 consecutive d's).
//   warps 0-3: forward, warp w covers d-locals {2w, 2w+1}
//   warps 4-7: backward, warp w-4 covers the same d pair
// Within a warp: lanes 0-15 = states of first d, lanes 16-31 = second d.
// ---------------------------------------------------------------------------
#define SCHUNK   64
#define SC_BUF   6272
#define SC_DU    4096
#define SC_SMEM  (2 * SC_BUF * 4)   // 50176 B

__global__ __launch_bounds__(256)
void scan_kernel(const float* __restrict__ A_log,
                 const float* __restrict__ Ab_log)
{
    extern __shared__ float ss[];
    const int b  = blockIdx.x / (DIN / 8);
    const int d0 = (blockIdx.x % (DIN / 8)) * 8;
    const int tid = threadIdx.x;
    const int wid = tid >> 5, lane = tid & 31;
    const bool bwd = wid >= 4;
    const int w = bwd ? wid - 4 : wid;
    const int half = lane >> 4, n = lane & 15;
    const int dloc = 2 * w + half;
    const int dg = d0 + dloc;

    const float Aval = -__expf(bwd ? Ab_log[dg * DSTATE + n]
                                   : A_log[dg * DSTATE + n]);
    float* yptr = (bwd ? g_yb : g_yf) + (size_t)(b * DIN + dg) * LEN;

    const uint32_t sbase = smem_u32(ss);

    auto load_chunk = [&](int c, int buf) {
        const uint32_t dstb = sbase + (uint32_t)buf * SC_BUF * 4;
        const int lf = c * SCHUNK;
        const int lb = LEN - (c + 1) * SCHUNK;
#pragma unroll
        for (int it = 0; it < 4; it++) {
            int task = it * 256 + tid;
            int arr = task >> 8, r = task & 255;
            int lo = r >> 2, n4 = (r & 3) * 4;
            int ls = (arr < 2) ? lf + lo : lb + lo;
            const float* src = ((arr & 1) ? g_Cm : g_Bm)
                + ((size_t)(b * LEN + ls) * DSTATE + n4);
            cp16(dstb + (uint32_t)(arr * 1024 + lo * 16 + n4) * 4, src);
        }
#pragma unroll
        for (int it = 0; it < 2; it++) {
            int q = it * 256 + tid;
            int arr = q >> 7, s = q & 127;
            int dl = s >> 4, l4 = (s & 15) * 4;
            int ls = (arr < 2) ? lf + l4 : lb + l4;
            const float* src = ((arr & 1) ? g_xc : g_delta)
                + ((size_t)(b * DIN + d0 + dl) * LEN + ls);
            cp16(dstb + (uint32_t)(SC_DU + arr * 544 + dl * 68 + l4) * 4, src);
        }
    };

    float h = 0.f;
    load_chunk(0, 0);
    CP_COMMIT();

    for (int c = 0; c < LEN / SCHUNK; c++) {
        const int buf = c & 1;
        if (c + 1 < LEN / SCHUNK) load_chunk(c + 1, buf ^ 1);
        CP_COMMIT();
        CP_WAIT1();
        __syncthreads();

        const float* sm   = ss + buf * SC_BUF;
        const float* sB   = sm + (bwd ? 2048 : 0);
        const float* sC   = sB + 1024;
        const float* sdel = sm + SC_DU + (bwd ? 1088 : 0) + dloc * 68;
        const float* su   = sdel + 544;

        if (!bwd) {
            const int tg = c * SCHUNK;
#pragma unroll
            for (int j4 = 0; j4 < 16; j4++) {
                float p[4];
#pragma unroll
                for (int k = 0; k < 4; k++) {
                    int t = j4 * 4 + k;
                    float del = sdel[t], u = su[t];
                    float Bv = sB[t * 16 + n], Cv = sC[t * 16 + n];
                    float dA = __expf(del * Aval);
                    h = fmaf(dA, h, del * u * Bv);
                    p[k] = h * Cv;
                }
#pragma unroll
                for (int k = 0; k < 4; k++) {
                    p[k] += __shfl_xor_sync(0xffffffffu, p[k], 1);
                    p[k] += __shfl_xor_sync(0xffffffffu, p[k], 2);
                    p[k] += __shfl_xor_sync(0xffffffffu, p[k], 4);
                    p[k] += __shfl_xor_sync(0xffffffffu, p[k], 8);
                }
                if (n == 0)
                    *(float4*)&yptr[tg + j4 * 4] =
                        make_float4(p[0], p[1], p[2], p[3]);
            }
        } else {
            const int tg = LEN - (c + 1) * SCHUNK;
#pragma unroll
            for (int j4 = 15; j4 >= 0; j4--) {
                float p[4];
#pragma unroll
                for (int k = 0; k < 4; k++) {
                    int t = j4 * 4 + (3 - k);
                    float del = sdel[t], u = su[t];
                    float Bv = sB[t * 16 + n], Cv = sC[t * 16 + n];
                    float dA = __expf(del * Aval);
                    h = fmaf(dA, h, del * u * Bv);
                    p[k] = h * Cv;
                }
#pragma unroll
                for (int k = 0; k < 4; k++) {
                    p[k] += __shfl_xor_sync(0xffffffffu, p[k], 1);
                    p[k] += __shfl_xor_sync(0xffffffffu, p[k], 2);
                    p[k] += __shfl_xor_sync(0xffffffffu, p[k], 4);
                    p[k] += __shfl_xor_sync(0xffffffffu, p[k], 8);
                }
                if (n == 0)
                    *(float4*)&yptr[tg + j4 * 4] =
                        make_float4(p[3], p[2], p[1], p[0]);
            }
        }
        __syncthreads();
    }
}

// ---------------------------------------------------------------------------
// fuse: g_yf = yf + yb + 2*D[d]*xc   (elementwise, (b,d,l) layout)
// ---------------------------------------------------------------------------
__global__ __launch_bounds__(256)
void fuse_kernel(const float* __restrict__ Dv)
{
    const int total4 = NB * DIN * LEN / 4;
    for (int i4 = blockIdx.x * blockDim.x + threadIdx.x; i4 < total4;
         i4 += gridDim.x * blockDim.x) {
        int d = (i4 >> 9) % DIN;
        float dd = 2.f * Dv[d];
        float4 yf4 = ((const float4*)g_yf)[i4];
        float4 yb4 = ((const float4*)g_yb)[i4];
        float4 xc4 = ((const float4*)g_xc)[i4];
        float4 o;
        o.x = yf4.x + yb4.x + dd * xc4.x;
        o.y = yf4.y + yb4.y + dd * xc4.y;
        o.z = yf4.z + yb4.z + dd * xc4.z;
        o.w = yf4.w + yb4.w + dd * xc4.w;
        ((float4*)g_yf)[i4] = o;
    }
}

// ---------------------------------------------------------------------------
// Launch
// ---------------------------------------------------------------------------
extern "C" void kernel_launch(void* const* d_in, const int* in_sizes, int n_in,
                              void* d_out, int out_size)
{
    (void)in_sizes; (void)n_in; (void)out_size;
    const float* x          = (const float*)d_in[0];
    const float* in_proj_w  = (const float*)d_in[1];
    const float* in_proj_b  = (const float*)d_in[2];
    const float* conv_w     = (const float*)d_in[3];
    const float* conv_b     = (const float*)d_in[4];
    const float* A_log      = (const float*)d_in[5];
    const float* Ab_log     = (const float*)d_in[6];
    const float* Dv         = (const float*)d_in[7];
    const float* x_proj_w   = (const float*)d_in[8];
    const float* dt_proj_w  = (const float*)d_in[9];
    const float* dt_proj_b  = (const float*)d_in[10];
    const float* out_proj_w = (const float*)d_in[11];
    const float* out_proj_b = (const float*)d_in[12];
    float* out = (float*)d_out;

    float* xp_ptr;
    cudaGetSymbolAddress((void**)&xp_ptr, g_xp);

    cudaFuncSetAttribute(gemm_tf32_kernel<0>,
                         cudaFuncAttributeMaxDynamicSharedMemorySize, GEMM_SMEM0);
    cudaFuncSetAttribute(gemm_tf32_kernel<1>,
                         cudaFuncAttributeMaxDynamicSharedMemorySize, GEMM_SMEM1);
    cudaFuncSetAttribute(scan_kernel,
                         cudaFuncAttributeMaxDynamicSharedMemorySize, SC_SMEM);

    // 1. in_proj GEMM (tf32 HMMA, 2-stage, 2 CTA/SM) -> g_xp
    gemm_tf32_kernel<0><<<dim3(DIM / 128, MTOT / 128), 256, GEMM_SMEM0>>>(
        x, in_proj_w, in_proj_b, xp_ptr);

    // 2. conv + silu -> g_xc
    conv_silu_kernel<<<dim3(LEN / 32, DIN / 32, NB), dim3(32, 32)>>>(
        conv_w, conv_b);

    // 3. x_proj split -> g_dt, g_Bm, g_Cm
    xproj_kernel<<<dim3(LEN / 128, NB, 4), 128>>>(x_proj_w);

    // 4. delta = softplus(dt_proj) -> g_delta   (profiled slot)
    delta_kernel<<<dim3(LEN / 128, NB, 8), 128>>>(dt_proj_w, dt_proj_b);

    // 5. bidirectional scan v2 -> g_yf, g_yb
    scan_kernel<<<NB * (DIN / 8), 256, SC_SMEM>>>(A_log, Ab_log);

    // 6. fuse ysum = yf + yb + 2*D*xc -> g_yf
    fuse_kernel<<<1024, 256>>>(Dv);

    // 7. out_proj GEMM (tf32 HMMA, 2-stage, (d,l)-layout A) -> d_out
    gemm_tf32_kernel<1><<<dim3(DIM / 128, MTOT / 128), 256, GEMM_SMEM1>>>(
        nullptr, out_proj_w, out_proj_b, out);
}